// round 5
// baseline (speedup 1.0000x reference)
#include <cuda_runtime.h>
#include <cuda_bf16.h>
#include <cstdint>

#define NB 16
#define NT 8192
#define NE 64
#define NC 128
#define GRID 152
#define NTILES 1024

// ---- per-buffer smem layout (bytes): rows stride 144, hi/lo split at +DLO ----
#define STR  144
#define DLO  18432
#define QOFF 0
#define KOFF 36864
#define VOFF 73728
#define BUFSZ 110592
#define SMEM_TOTAL (2 * BUFSZ)     // 221184 B = 216 KB (< 227 KB cap)

#define QSCALE 0.18033688011112042f   // (1/8) * log2(e): softmax via ex2

__device__ __forceinline__ uint32_t smem_u32(const void* p) {
    uint32_t a;
    asm("{ .reg .u64 t; cvta.to.shared.u64 t, %1; cvt.u32.u64 %0, t; }" : "=r"(a) : "l"(p));
    return a;
}
__device__ __forceinline__ uint32_t pk2(float a, float b) {
    __nv_bfloat162 t = __floats2bfloat162_rn(a, b);
    return *(uint32_t*)&t;
}
__device__ __forceinline__ float2 unpk2(uint32_t u) {
    __nv_bfloat162 t = *(__nv_bfloat162*)&u;
    return make_float2(__bfloat162float(t.x), __bfloat162float(t.y));
}
__device__ __forceinline__ float ex2a(float x) {
    float r; asm("ex2.approx.f32 %0, %1;" : "=f"(r) : "f"(x)); return r;
}

#define MMA16816(d0,d1,d2,d3,a0,a1,a2,a3,b0,b1)                              \
    asm volatile("mma.sync.aligned.m16n8k16.row.col.f32.bf16.bf16.f32 "      \
                 "{%0,%1,%2,%3}, {%4,%5,%6,%7}, {%8,%9}, {%0,%1,%2,%3};"     \
                 : "+f"(d0), "+f"(d1), "+f"(d2), "+f"(d3)                    \
                 : "r"(a0), "r"(a1), "r"(a2), "r"(a3), "r"(b0), "r"(b1))

#define LDSM4(r0,r1,r2,r3,addr)                                              \
    asm volatile("ldmatrix.sync.aligned.m8n8.x4.shared.b16 {%0,%1,%2,%3}, [%4];" \
                 : "=r"(r0), "=r"(r1), "=r"(r2), "=r"(r3) : "r"(addr))

#define LDSM4T(r0,r1,r2,r3,addr)                                             \
    asm volatile("ldmatrix.sync.aligned.m8n8.x4.trans.shared.b16 {%0,%1,%2,%3}, [%4];" \
                 : "=r"(r0), "=r"(r1), "=r"(r2), "=r"(r3) : "r"(addr))

// ---------------- consumer: one warp, 16 rows, Np = 16G columns ----------------
template<int G>
__device__ __forceinline__ void consume(uint32_t buf, int R, int lane, int i0,
                                        float* __restrict__ OutB, float* __restrict__ AB)
{
    const int g  = lane >> 2;
    const int tg = lane & 3;
    const int nv_lo = (i0 + R + g + 1) >> 6;
    const int nv_hi = (i0 + R + g + 8 + 1) >> 6;

    // ---- Q fragments via ldmatrix (A operand) ----
    uint32_t qh[4][4], ql[4][4];
    {
        const uint32_t qa = buf + QOFF +
            (uint32_t)((R + (lane & 7) + ((lane >> 3) & 1) * 8) * STR + (lane >> 4) * 16);
#pragma unroll
        for (int k = 0; k < 4; ++k) {
            LDSM4(qh[k][0], qh[k][1], qh[k][2], qh[k][3], qa + 32 * k);
            LDSM4(ql[k][0], ql[k][1], ql[k][2], ql[k][3], qa + DLO + 32 * k);
        }
    }

    const uint32_t ka = buf + KOFF + (uint32_t)((lane & 7) * STR + (lane >> 3) * 16);
    const uint32_t va = buf + VOFF +
        (uint32_t)(((lane & 7) + ((lane >> 3) & 1) * 8) * STR + (lane >> 4) * 16);

    uint32_t p01h[2 * G], p01l[2 * G], p23h[2 * G], p23l[2 * G];
    float sum_lo = 0.0f, sum_hi = 0.0f;

    // ---- MMA1: S (log2-domain) then exp via ex2 ----
#pragma unroll
    for (int n = 0; n < 2 * G; ++n) {
        const uint32_t kan = ka + (uint32_t)(n * 8 * STR);
        uint32_t kh[8], kl[8];
        LDSM4(kh[0], kh[1], kh[2], kh[3], kan);
        LDSM4(kh[4], kh[5], kh[6], kh[7], kan + 64);
        LDSM4(kl[0], kl[1], kl[2], kl[3], kan + DLO);
        LDSM4(kl[4], kl[5], kl[6], kl[7], kan + DLO + 64);

        float dA[4] = {0.f, 0.f, 0.f, 0.f};
        float dB[4] = {0.f, 0.f, 0.f, 0.f};
        float dC[4] = {0.f, 0.f, 0.f, 0.f};
#pragma unroll
        for (int k = 0; k < 4; ++k)
            MMA16816(dA[0], dA[1], dA[2], dA[3],
                     qh[k][0], qh[k][1], qh[k][2], qh[k][3], kh[2 * k], kh[2 * k + 1]);
#pragma unroll
        for (int k = 0; k < 4; ++k)
            MMA16816(dB[0], dB[1], dB[2], dB[3],
                     qh[k][0], qh[k][1], qh[k][2], qh[k][3], kl[2 * k], kl[2 * k + 1]);
#pragma unroll
        for (int k = 0; k < 4; ++k)
            MMA16816(dC[0], dC[1], dC[2], dC[3],
                     ql[k][0], ql[k][1], ql[k][2], ql[k][3], kh[2 * k], kh[2 * k + 1]);

        const float d0 = dA[0] + dB[0] + dC[0];
        const float d1 = dA[1] + dB[1] + dC[1];
        const float d2 = dA[2] + dB[2] + dC[2];
        const float d3 = dA[3] + dB[3] + dC[3];

        const int j0 = 8 * n + 2 * tg;
        const float e0 = (j0     < nv_lo) ? ex2a(d0) : 0.0f;
        const float e1 = (j0 + 1 < nv_lo) ? ex2a(d1) : 0.0f;
        const float e2 = (j0     < nv_hi) ? ex2a(d2) : 0.0f;
        const float e3 = (j0 + 1 < nv_hi) ? ex2a(d3) : 0.0f;
        sum_lo += e0 + e1;
        sum_hi += e2 + e3;
        p01h[n] = pk2(e0, e1); { float2 r = unpk2(p01h[n]); p01l[n] = pk2(e0 - r.x, e1 - r.y); }
        p23h[n] = pk2(e2, e3); { float2 r = unpk2(p23h[n]); p23l[n] = pk2(e2 - r.x, e3 - r.y); }
    }

    sum_lo += __shfl_xor_sync(0xffffffffu, sum_lo, 1);
    sum_lo += __shfl_xor_sync(0xffffffffu, sum_lo, 2);
    sum_hi += __shfl_xor_sync(0xffffffffu, sum_hi, 1);
    sum_hi += __shfl_xor_sync(0xffffffffu, sum_hi, 2);
    const float inv_lo = (nv_lo > 0) ? 1.0f / sum_lo : 0.0f;
    const float inv_hi = (nv_hi > 0) ? 1.0f / sum_hi : 0.0f;

    // ---- MMA2: Out = Ehat * V ----
    float o[8][4];
#pragma unroll
    for (int nt = 0; nt < 8; ++nt)
#pragma unroll
        for (int t = 0; t < 4; ++t) o[nt][t] = 0.0f;

#pragma unroll
    for (int kk = 0; kk < G; ++kk) {
        const uint32_t ah0 = p01h[2 * kk], ah1 = p23h[2 * kk];
        const uint32_t ah2 = p01h[2 * kk + 1], ah3 = p23h[2 * kk + 1];
        const uint32_t al0 = p01l[2 * kk], al1 = p23l[2 * kk];
        const uint32_t al2 = p01l[2 * kk + 1], al3 = p23l[2 * kk + 1];
        const uint32_t vak = va + (uint32_t)(kk * 16 * STR);

        uint32_t vh[16];
        LDSM4T(vh[0],  vh[1],  vh[2],  vh[3],  vak);
        LDSM4T(vh[4],  vh[5],  vh[6],  vh[7],  vak + 32);
        LDSM4T(vh[8],  vh[9],  vh[10], vh[11], vak + 64);
        LDSM4T(vh[12], vh[13], vh[14], vh[15], vak + 96);
#pragma unroll
        for (int nt = 0; nt < 8; ++nt) {
            const uint32_t b0 = vh[(nt >> 1) * 4 + (nt & 1) * 2];
            const uint32_t b1 = vh[(nt >> 1) * 4 + (nt & 1) * 2 + 1];
            MMA16816(o[nt][0], o[nt][1], o[nt][2], o[nt][3], ah0, ah1, ah2, ah3, b0, b1);
        }
#pragma unroll
        for (int nt = 0; nt < 8; ++nt) {
            const uint32_t b0 = vh[(nt >> 1) * 4 + (nt & 1) * 2];
            const uint32_t b1 = vh[(nt >> 1) * 4 + (nt & 1) * 2 + 1];
            MMA16816(o[nt][0], o[nt][1], o[nt][2], o[nt][3], al0, al1, al2, al3, b0, b1);
        }
        uint32_t vl[16];
        LDSM4T(vl[0],  vl[1],  vl[2],  vl[3],  vak + DLO);
        LDSM4T(vl[4],  vl[5],  vl[6],  vl[7],  vak + DLO + 32);
        LDSM4T(vl[8],  vl[9],  vl[10], vl[11], vak + DLO + 64);
        LDSM4T(vl[12], vl[13], vl[14], vl[15], vak + DLO + 96);
#pragma unroll
        for (int nt = 0; nt < 8; ++nt) {
            const uint32_t b0 = vl[(nt >> 1) * 4 + (nt & 1) * 2];
            const uint32_t b1 = vl[(nt >> 1) * 4 + (nt & 1) * 2 + 1];
            MMA16816(o[nt][0], o[nt][1], o[nt][2], o[nt][3], ah0, ah1, ah2, ah3, b0, b1);
        }
    }

    // ---- write Out (normalized) ----
#pragma unroll
    for (int nt = 0; nt < 8; ++nt) {
        const int e = 8 * nt + 2 * tg;
        *(float2*)(OutB + (size_t)(R + g) * NE + e)     = make_float2(o[nt][0] * inv_lo, o[nt][1] * inv_lo);
        *(float2*)(OutB + (size_t)(R + g + 8) * NE + e) = make_float2(o[nt][2] * inv_hi, o[nt][3] * inv_hi);
    }
    // ---- write A (normalized, hi+lo reconstructed) ----
#pragma unroll
    for (int n = 0; n < 2 * G; ++n) {
        const int j = 8 * n + 2 * tg;
        float2 h = unpk2(p01h[n]), l = unpk2(p01l[n]);
        *(float2*)(AB + (size_t)(R + g) * NC + j) =
            make_float2((h.x + l.x) * inv_lo, (h.y + l.y) * inv_lo);
        h = unpk2(p23h[n]); l = unpk2(p23l[n]);
        *(float2*)(AB + (size_t)(R + g + 8) * NC + j) =
            make_float2((h.x + l.x) * inv_hi, (h.y + l.y) * inv_hi);
    }
    // ---- zero tail columns [16G, 128) of A ----
    if (G < 8) {
        const int Np = 16 * G;
        const int t4 = (NC - Np) >> 2;
        for (int t = lane; t < 16 * t4; t += 32) {
            const int row = t / t4, cq = t - row * t4;
            *(float4*)(AB + (size_t)(R + row) * NC + Np + 4 * cq) =
                make_float4(0.f, 0.f, 0.f, 0.f);
        }
    }
}

// ---------------- producer: 256 threads stage one tile into a buffer ----------------
__device__ __forceinline__ void produce(char* sm, int bufidx, int m, int ptid,
                                        const float* __restrict__ Qg,
                                        const float* __restrict__ Kg,
                                        const float* __restrict__ Vg)
{
    const int p  = 63 - (m >> 4);
    const int b  = m & 15;
    const int c  = 2 * p + 2;
    const int Np = ((c + 15) & ~15);
    const int i0 = p << 7;
    char* buf = sm + bufidx * BUFSZ;

    // ---- Q: 128 rows, pre-scaled into log2 domain ----
    {
        const float* Qb = Qg + (size_t)(b * NT + i0) * NE;
#pragma unroll
        for (int u = 0; u < 8; ++u) {
            const int idx = ptid + u * 256;
            const int rr = idx >> 4, e4 = (idx & 15) << 2;
            float4 q = *(const float4*)(Qb + (size_t)rr * NE + e4);
            q.x *= QSCALE; q.y *= QSCALE; q.z *= QSCALE; q.w *= QSCALE;
            const uint32_t h01 = pk2(q.x, q.y), h23 = pk2(q.z, q.w);
            float2 r01 = unpk2(h01), r23 = unpk2(h23);
            const uint32_t l01 = pk2(q.x - r01.x, q.y - r01.y);
            const uint32_t l23 = pk2(q.z - r23.x, q.w - r23.y);
            char* dst = buf + QOFF + rr * STR + e4 * 2;
            *(uint2*)dst         = make_uint2(h01, h23);
            *(uint2*)(dst + DLO) = make_uint2(l01, l23);
        }
    }
    // ---- K and V gathered rows ----
    {
        const float* Kb = Kg + (size_t)b * NT * NE + (size_t)63 * NE;
        const float* Vb = Vg + (size_t)b * NT * NE + (size_t)63 * NE;
        const int tot = c * 16;
#pragma unroll
        for (int u = 0; u < 8; ++u) {
            const int idx = ptid + u * 256;
            if (idx < tot) {
                const int j = idx >> 4, e4 = (idx & 15) << 2;
                const size_t goff = (size_t)j * 64 * NE + e4;
                {
                    const float4 k4 = *(const float4*)(Kb + goff);
                    const uint32_t h01 = pk2(k4.x, k4.y), h23 = pk2(k4.z, k4.w);
                    float2 r01 = unpk2(h01), r23 = unpk2(h23);
                    const uint32_t l01 = pk2(k4.x - r01.x, k4.y - r01.y);
                    const uint32_t l23 = pk2(k4.z - r23.x, k4.w - r23.y);
                    char* dst = buf + KOFF + j * STR + e4 * 2;
                    *(uint2*)dst         = make_uint2(h01, h23);
                    *(uint2*)(dst + DLO) = make_uint2(l01, l23);
                }
                {
                    const float4 v4 = *(const float4*)(Vb + goff);
                    const uint32_t h01 = pk2(v4.x, v4.y), h23 = pk2(v4.z, v4.w);
                    float2 r01 = unpk2(h01), r23 = unpk2(h23);
                    const uint32_t l01 = pk2(v4.x - r01.x, v4.y - r01.y);
                    const uint32_t l23 = pk2(v4.z - r23.x, v4.w - r23.y);
                    char* dst = buf + VOFF + j * STR + e4 * 2;
                    *(uint2*)dst         = make_uint2(h01, h23);
                    *(uint2*)(dst + DLO) = make_uint2(l01, l23);
                }
            }
        }
        // zero pad rows [c, Np)
        for (int idx = ptid; idx < (Np - c) * 16; idx += 256) {
            const int j = c + (idx >> 4), e4 = (idx & 15) << 2;
            char* dk = buf + KOFF + j * STR + e4 * 2;
            char* dv = buf + VOFF + j * STR + e4 * 2;
            *(uint2*)dk         = make_uint2(0u, 0u);
            *(uint2*)(dk + DLO) = make_uint2(0u, 0u);
            *(uint2*)dv         = make_uint2(0u, 0u);
            *(uint2*)(dv + DLO) = make_uint2(0u, 0u);
        }
    }
}

// ---------------- persistent kernel ----------------
__global__ __launch_bounds__(512, 1)
void cba_pers(const float* __restrict__ Qg, const float* __restrict__ Kg,
              const float* __restrict__ Vg, float* __restrict__ Outg,
              float* __restrict__ Ag)
{
    extern __shared__ char sm[];
    const int tid  = (int)threadIdx.x;
    const int cta  = (int)blockIdx.x;
    const int nT   = (NTILES - 1 - cta) / GRID + 1;
    const bool prod = (tid >= 256);
    const int ptid = tid - 256;
    const int lane = tid & 31;
    const int w    = tid >> 5;          // consumer warp 0..7
    const uint32_t smb = smem_u32(sm);

    if (prod) produce(sm, 0, cta, ptid, Qg, Kg, Vg);

    for (int t = 0; t < nT; ++t) {
        __syncthreads();                 // buf[t&1] ready; buf[(t+1)&1] free
        if (prod) {
            if (t + 1 < nT)
                produce(sm, (t + 1) & 1, cta + (t + 1) * GRID, ptid, Qg, Kg, Vg);
        } else {
            const int m  = cta + t * GRID;
            const int p  = 63 - (m >> 4);
            const int b  = m & 15;
            const int G  = ((2 * p + 2) + 15) >> 4;
            const int i0 = p << 7;
            const uint32_t buf = smb + (uint32_t)((t & 1) * BUFSZ);
            float* OutB = Outg + (size_t)(b * NT + i0) * NE;
            float* AB   = Ag   + (size_t)(b * NT + i0) * NC;
            const int R = w << 4;
            switch (G) {
            case 1: consume<1>(buf, R, lane, i0, OutB, AB); break;
            case 2: consume<2>(buf, R, lane, i0, OutB, AB); break;
            case 3: consume<3>(buf, R, lane, i0, OutB, AB); break;
            case 4: consume<4>(buf, R, lane, i0, OutB, AB); break;
            case 5: consume<5>(buf, R, lane, i0, OutB, AB); break;
            case 6: consume<6>(buf, R, lane, i0, OutB, AB); break;
            case 7: consume<7>(buf, R, lane, i0, OutB, AB); break;
            default: consume<8>(buf, R, lane, i0, OutB, AB); break;
            }
        }
    }
}

extern "C" void kernel_launch(void* const* d_in, const int* in_sizes, int n_in,
                              void* d_out, int out_size)
{
    const float* Q = (const float*)d_in[0];
    const float* K = (const float*)d_in[1];
    const float* V = (const float*)d_in[2];
    float* Out = (float*)d_out;
    float* A   = Out + (size_t)NB * NT * NE;

    cudaFuncSetAttribute(cba_pers, cudaFuncAttributeMaxDynamicSharedMemorySize, SMEM_TOTAL);
    cba_pers<<<GRID, 512, SMEM_TOTAL>>>(Q, K, V, Out, A);
}

// round 6
// speedup vs baseline: 1.5093x; 1.5093x over previous
#include <cuda_runtime.h>
#include <cuda_bf16.h>
#include <cstdint>

#define NB 16
#define NT 8192
#define NE 64
#define NC 128

// ---- smem layout: K and V row images [j][72 bf16], hi/lo split at +DLO ----
#define STR  144
#define KHI  0
#define KLO  18432
#define VHI  36864
#define VLO  55296
#define DLO  18432
#define SMEM_TOTAL 73728

#define QSCALE 0.18033688011112042f   // (1/8) * log2(e): softmax via ex2

// ---- pre-split gathered K/V scratch: exact 144B smem row images ----
__device__ __align__(16) char g_ksh[NB * 128 * STR];
__device__ __align__(16) char g_ksl[NB * 128 * STR];
__device__ __align__(16) char g_vsh[NB * 128 * STR];
__device__ __align__(16) char g_vsl[NB * 128 * STR];

__device__ __forceinline__ uint32_t smem_u32(const void* p) {
    uint32_t a;
    asm("{ .reg .u64 t; cvta.to.shared.u64 t, %1; cvt.u32.u64 %0, t; }" : "=r"(a) : "l"(p));
    return a;
}
__device__ __forceinline__ uint32_t pk2(float a, float b) {
    __nv_bfloat162 t = __floats2bfloat162_rn(a, b);
    return *(uint32_t*)&t;
}
__device__ __forceinline__ float2 unpk2(uint32_t u) {
    __nv_bfloat162 t = *(__nv_bfloat162*)&u;
    return make_float2(__bfloat162float(t.x), __bfloat162float(t.y));
}
__device__ __forceinline__ float ex2a(float x) {
    float r; asm("ex2.approx.f32 %0, %1;" : "=f"(r) : "f"(x)); return r;
}
#define CP16(dst, src)                                                       \
    asm volatile("cp.async.cg.shared.global [%0], [%1], 16;"                 \
                 :: "r"(dst), "l"(src) : "memory")

#define MMA16816(d0,d1,d2,d3,a0,a1,a2,a3,b0,b1)                              \
    asm volatile("mma.sync.aligned.m16n8k16.row.col.f32.bf16.bf16.f32 "      \
                 "{%0,%1,%2,%3}, {%4,%5,%6,%7}, {%8,%9}, {%0,%1,%2,%3};"     \
                 : "+f"(d0), "+f"(d1), "+f"(d2), "+f"(d3)                    \
                 : "r"(a0), "r"(a1), "r"(a2), "r"(a3), "r"(b0), "r"(b1))

#define LDSM4(r0,r1,r2,r3,addr)                                              \
    asm volatile("ldmatrix.sync.aligned.m8n8.x4.shared.b16 {%0,%1,%2,%3}, [%4];" \
                 : "=r"(r0), "=r"(r1), "=r"(r2), "=r"(r3) : "r"(addr))

#define LDSM4T(r0,r1,r2,r3,addr)                                             \
    asm volatile("ldmatrix.sync.aligned.m8n8.x4.trans.shared.b16 {%0,%1,%2,%3}, [%4];" \
                 : "=r"(r0), "=r"(r1), "=r"(r2), "=r"(r3) : "r"(addr))

// ---------------- pre-pass: split gathered K/V into scratch row images ----------------
__global__ __launch_bounds__(256)
void cba_prep(const float* __restrict__ Kg, const float* __restrict__ Vg)
{
    const int u = (int)blockIdx.x * 256 + (int)threadIdx.x;   // 16*128*16 units
    const int b = u >> 11;
    const int rem = u & 2047;
    const int j = rem >> 4;
    const int e4 = (rem & 15) << 2;
    const size_t goff = ((size_t)(b * NT + 64 * j + 63)) * NE + e4;
    const size_t soff = (size_t)(b * 128 + j) * STR + e4 * 2;

    {
        const float4 k4 = *(const float4*)(Kg + goff);
        const uint32_t h01 = pk2(k4.x, k4.y), h23 = pk2(k4.z, k4.w);
        float2 r01 = unpk2(h01), r23 = unpk2(h23);
        *(uint2*)(g_ksh + soff) = make_uint2(h01, h23);
        *(uint2*)(g_ksl + soff) = make_uint2(pk2(k4.x - r01.x, k4.y - r01.y),
                                             pk2(k4.z - r23.x, k4.w - r23.y));
    }
    {
        const float4 v4 = *(const float4*)(Vg + goff);
        const uint32_t h01 = pk2(v4.x, v4.y), h23 = pk2(v4.z, v4.w);
        float2 r01 = unpk2(h01), r23 = unpk2(h23);
        *(uint2*)(g_vsh + soff) = make_uint2(h01, h23);
        *(uint2*)(g_vsl + soff) = make_uint2(pk2(v4.x - r01.x, v4.y - r01.y),
                                             pk2(v4.z - r23.x, v4.w - r23.y));
    }
}

// ---------------- consumer: one warp, 16 rows, Np = 16G columns ----------------
template<int G>
__device__ __forceinline__ void warp_work(uint32_t smb, int R, int lane, int i0,
                                          const uint32_t qh[4][4], const uint32_t ql[4][4],
                                          float* __restrict__ OutB, float* __restrict__ AB)
{
    const int g  = lane >> 2;
    const int tg = lane & 3;
    const int nv_lo = (i0 + R + g + 1) >> 6;
    const int nv_hi = (i0 + R + g + 8 + 1) >> 6;

    const uint32_t ka = smb + KHI + (uint32_t)((lane & 7) * STR + (lane >> 3) * 16);
    const uint32_t va = smb + VHI +
        (uint32_t)(((lane & 7) + ((lane >> 3) & 1) * 8) * STR + (lane >> 4) * 16);

    uint32_t p01h[2 * G], p01l[2 * G], p23h[2 * G], p23l[2 * G];
    float sum_lo = 0.0f, sum_hi = 0.0f;

    // ---- MMA1: 3 independent 4-chains per n-tile; S in log2 domain ----
#pragma unroll
    for (int n = 0; n < 2 * G; ++n) {
        const uint32_t kan = ka + (uint32_t)(n * 8 * STR);
        uint32_t kh[8], kl[8];
        LDSM4(kh[0], kh[1], kh[2], kh[3], kan);
        LDSM4(kh[4], kh[5], kh[6], kh[7], kan + 64);
        LDSM4(kl[0], kl[1], kl[2], kl[3], kan + DLO);
        LDSM4(kl[4], kl[5], kl[6], kl[7], kan + DLO + 64);

        float dA[4] = {0.f, 0.f, 0.f, 0.f};
        float dB[4] = {0.f, 0.f, 0.f, 0.f};
        float dC[4] = {0.f, 0.f, 0.f, 0.f};
#pragma unroll
        for (int k = 0; k < 4; ++k)
            MMA16816(dA[0], dA[1], dA[2], dA[3],
                     qh[k][0], qh[k][1], qh[k][2], qh[k][3], kh[2 * k], kh[2 * k + 1]);
#pragma unroll
        for (int k = 0; k < 4; ++k)
            MMA16816(dB[0], dB[1], dB[2], dB[3],
                     qh[k][0], qh[k][1], qh[k][2], qh[k][3], kl[2 * k], kl[2 * k + 1]);
#pragma unroll
        for (int k = 0; k < 4; ++k)
            MMA16816(dC[0], dC[1], dC[2], dC[3],
                     ql[k][0], ql[k][1], ql[k][2], ql[k][3], kh[2 * k], kh[2 * k + 1]);

        const float d0 = dA[0] + dB[0] + dC[0];
        const float d1 = dA[1] + dB[1] + dC[1];
        const float d2 = dA[2] + dB[2] + dC[2];
        const float d3 = dA[3] + dB[3] + dC[3];

        const int j0 = 8 * n + 2 * tg;
        const float e0 = (j0     < nv_lo) ? ex2a(d0) : 0.0f;
        const float e1 = (j0 + 1 < nv_lo) ? ex2a(d1) : 0.0f;
        const float e2 = (j0     < nv_hi) ? ex2a(d2) : 0.0f;
        const float e3 = (j0 + 1 < nv_hi) ? ex2a(d3) : 0.0f;
        sum_lo += e0 + e1;
        sum_hi += e2 + e3;
        p01h[n] = pk2(e0, e1); { float2 r = unpk2(p01h[n]); p01l[n] = pk2(e0 - r.x, e1 - r.y); }
        p23h[n] = pk2(e2, e3); { float2 r = unpk2(p23h[n]); p23l[n] = pk2(e2 - r.x, e3 - r.y); }
    }

    sum_lo += __shfl_xor_sync(0xffffffffu, sum_lo, 1);
    sum_lo += __shfl_xor_sync(0xffffffffu, sum_lo, 2);
    sum_hi += __shfl_xor_sync(0xffffffffu, sum_hi, 1);
    sum_hi += __shfl_xor_sync(0xffffffffu, sum_hi, 2);
    const float inv_lo = (nv_lo > 0) ? 1.0f / sum_lo : 0.0f;
    const float inv_hi = (nv_hi > 0) ? 1.0f / sum_hi : 0.0f;

    // ---- MMA2: Out = Ehat * V ----
    float o[8][4];
#pragma unroll
    for (int nt = 0; nt < 8; ++nt)
#pragma unroll
        for (int t = 0; t < 4; ++t) o[nt][t] = 0.0f;

#pragma unroll
    for (int kk = 0; kk < G; ++kk) {
        const uint32_t ah0 = p01h[2 * kk], ah1 = p23h[2 * kk];
        const uint32_t ah2 = p01h[2 * kk + 1], ah3 = p23h[2 * kk + 1];
        const uint32_t al0 = p01l[2 * kk], al1 = p23l[2 * kk];
        const uint32_t al2 = p01l[2 * kk + 1], al3 = p23l[2 * kk + 1];
        const uint32_t vak = va + (uint32_t)(kk * 16 * STR);

        uint32_t vh[16];
        LDSM4T(vh[0],  vh[1],  vh[2],  vh[3],  vak);
        LDSM4T(vh[4],  vh[5],  vh[6],  vh[7],  vak + 32);
        LDSM4T(vh[8],  vh[9],  vh[10], vh[11], vak + 64);
        LDSM4T(vh[12], vh[13], vh[14], vh[15], vak + 96);
#pragma unroll
        for (int nt = 0; nt < 8; ++nt) {
            const uint32_t b0 = vh[(nt >> 1) * 4 + (nt & 1) * 2];
            const uint32_t b1 = vh[(nt >> 1) * 4 + (nt & 1) * 2 + 1];
            MMA16816(o[nt][0], o[nt][1], o[nt][2], o[nt][3], ah0, ah1, ah2, ah3, b0, b1);
        }
#pragma unroll
        for (int nt = 0; nt < 8; ++nt) {
            const uint32_t b0 = vh[(nt >> 1) * 4 + (nt & 1) * 2];
            const uint32_t b1 = vh[(nt >> 1) * 4 + (nt & 1) * 2 + 1];
            MMA16816(o[nt][0], o[nt][1], o[nt][2], o[nt][3], al0, al1, al2, al3, b0, b1);
        }
        uint32_t vl[16];
        LDSM4T(vl[0],  vl[1],  vl[2],  vl[3],  vak + DLO);
        LDSM4T(vl[4],  vl[5],  vl[6],  vl[7],  vak + DLO + 32);
        LDSM4T(vl[8],  vl[9],  vl[10], vl[11], vak + DLO + 64);
        LDSM4T(vl[12], vl[13], vl[14], vl[15], vak + DLO + 96);
#pragma unroll
        for (int nt = 0; nt < 8; ++nt) {
            const uint32_t b0 = vl[(nt >> 1) * 4 + (nt & 1) * 2];
            const uint32_t b1 = vl[(nt >> 1) * 4 + (nt & 1) * 2 + 1];
            MMA16816(o[nt][0], o[nt][1], o[nt][2], o[nt][3], ah0, ah1, ah2, ah3, b0, b1);
        }
    }

    // ---- write Out (normalized) ----
#pragma unroll
    for (int nt = 0; nt < 8; ++nt) {
        const int e = 8 * nt + 2 * tg;
        *(float2*)(OutB + (size_t)(R + g) * NE + e)     = make_float2(o[nt][0] * inv_lo, o[nt][1] * inv_lo);
        *(float2*)(OutB + (size_t)(R + g + 8) * NE + e) = make_float2(o[nt][2] * inv_hi, o[nt][3] * inv_hi);
    }
    // ---- write A (normalized, hi+lo reconstructed) ----
#pragma unroll
    for (int n = 0; n < 2 * G; ++n) {
        const int j = 8 * n + 2 * tg;
        float2 h = unpk2(p01h[n]), l = unpk2(p01l[n]);
        *(float2*)(AB + (size_t)(R + g) * NC + j) =
            make_float2((h.x + l.x) * inv_lo, (h.y + l.y) * inv_lo);
        h = unpk2(p23h[n]); l = unpk2(p23l[n]);
        *(float2*)(AB + (size_t)(R + g + 8) * NC + j) =
            make_float2((h.x + l.x) * inv_hi, (h.y + l.y) * inv_hi);
    }
    // ---- zero tail columns [16G, 128) of A ----
    if (G < 8) {
        const int Np = 16 * G;
        const int t4 = (NC - Np) >> 2;
        for (int t = lane; t < 16 * t4; t += 32) {
            const int row = t / t4, cq = t - row * t4;
            *(float4*)(AB + (size_t)(R + row) * NC + Np + 4 * cq) =
                make_float4(0.f, 0.f, 0.f, 0.f);
        }
    }
}

// ---------------- main kernel ----------------
__global__ __launch_bounds__(256, 2)
void cba_mma(const float* __restrict__ Qg, float* __restrict__ Outg,
             float* __restrict__ Ag)
{
    extern __shared__ char sm[];
    const int tid  = (int)threadIdx.x;
    const int lane = tid & 31;
    const int w    = tid >> 5;
    const int p    = 63 - (int)blockIdx.x;
    const int b    = (int)blockIdx.y;
    const int c    = 2 * p + 2;
    const int G    = (c + 15) >> 4;
    const int Np   = G << 4;
    const int i0   = p << 7;
    const int g    = lane >> 2;
    const int tg   = lane & 3;
    const int R    = w << 4;
    const uint32_t smb = smem_u32(sm);

    // ---- issue Q fragment loads early ----
    float2 qf[4][4];
    {
        const float* Qb = Qg + (size_t)(b * NT + i0) * NE;
#pragma unroll
        for (int k = 0; k < 4; ++k) {
            const float* q0 = Qb + (size_t)(R + g) * NE + 16 * k + 2 * tg;
            const float* q8 = q0 + 8 * NE;
            qf[k][0] = *(const float2*)q0;
            qf[k][1] = *(const float2*)q8;
            qf[k][2] = *(const float2*)(q0 + 8);
            qf[k][3] = *(const float2*)(q8 + 8);
        }
    }

    // ---- stage K/V via cp.async from pre-split scratch (no regs, no cvt) ----
    {
        const size_t boff = (size_t)b * 128 * STR;
        const char* kh = g_ksh + boff;
        const char* kl = g_ksl + boff;
        const char* vh = g_vsh + boff;
        const char* vl = g_vsl + boff;
        const int nchunk = c * 9;               // 16B chunks per region
        for (int idx = tid; idx < nchunk; idx += 256) {
            const uint32_t off = (uint32_t)idx * 16;
            CP16(smb + KHI + off, kh + off);
            CP16(smb + KLO + off, kl + off);
            CP16(smb + VHI + off, vh + off);
            CP16(smb + VLO + off, vl + off);
        }
        asm volatile("cp.async.commit_group;" ::: "memory");
        // zero pad rows [c, Np) in all regions (V pads are load-bearing)
        const int padchunk = (Np - c) * 9;
        for (int idx = tid; idx < padchunk; idx += 256) {
            const uint32_t off = (uint32_t)(c * 9 + idx) * 16;
            *(uint4*)(sm + KHI + off) = make_uint4(0u, 0u, 0u, 0u);
            *(uint4*)(sm + KLO + off) = make_uint4(0u, 0u, 0u, 0u);
            *(uint4*)(sm + VHI + off) = make_uint4(0u, 0u, 0u, 0u);
            *(uint4*)(sm + VLO + off) = make_uint4(0u, 0u, 0u, 0u);
        }
    }

    // ---- convert Q to bf16 hi/lo fragments (log2-domain prescale) ----
    uint32_t qh[4][4], ql[4][4];
#pragma unroll
    for (int k = 0; k < 4; ++k)
#pragma unroll
        for (int t = 0; t < 4; ++t) {
            const float x = qf[k][t].x * QSCALE, y = qf[k][t].y * QSCALE;
            qh[k][t] = pk2(x, y);
            float2 r = unpk2(qh[k][t]);
            ql[k][t] = pk2(x - r.x, y - r.y);
        }

    asm volatile("cp.async.wait_group 0;" ::: "memory");
    __syncthreads();

    float* OutB = Outg + (size_t)(b * NT + i0) * NE;
    float* AB   = Ag   + (size_t)(b * NT + i0) * NC;

    switch (G) {
    case 1: warp_work<1>(smb, R, lane, i0, qh, ql, OutB, AB); break;
    case 2: warp_work<2>(smb, R, lane, i0, qh, ql, OutB, AB); break;
    case 3: warp_work<3>(smb, R, lane, i0, qh, ql, OutB, AB); break;
    case 4: warp_work<4>(smb, R, lane, i0, qh, ql, OutB, AB); break;
    case 5: warp_work<5>(smb, R, lane, i0, qh, ql, OutB, AB); break;
    case 6: warp_work<6>(smb, R, lane, i0, qh, ql, OutB, AB); break;
    case 7: warp_work<7>(smb, R, lane, i0, qh, ql, OutB, AB); break;
    default: warp_work<8>(smb, R, lane, i0, qh, ql, OutB, AB); break;
    }
}

extern "C" void kernel_launch(void* const* d_in, const int* in_sizes, int n_in,
                              void* d_out, int out_size)
{
    const float* Q = (const float*)d_in[0];
    const float* K = (const float*)d_in[1];
    const float* V = (const float*)d_in[2];
    float* Out = (float*)d_out;
    float* A   = Out + (size_t)NB * NT * NE;

    cba_prep<<<128, 256>>>(K, V);

    cudaFuncSetAttribute(cba_mma, cudaFuncAttributeMaxDynamicSharedMemorySize, SMEM_TOTAL);
    dim3 grid(64, NB);
    cba_mma<<<grid, 256, SMEM_TOTAL>>>(Q, Out, A);
}

// round 7
// speedup vs baseline: 2.2680x; 1.5027x over previous
#include <cuda_runtime.h>
#include <cuda_fp16.h>
#include <cstdint>

#define NB 16
#define NT 8192
#define NE 64
#define NC 128

// ---- smem layout: K and V row images [j][72 fp16] ----
#define STR  144
#define KOFF 0
#define VOFF 18432
#define SMEM_TOTAL 36864

#define QSCALE 0.18033688011112042f   // (1/8) * log2(e): softmax via ex2

// ---- pre-converted gathered K/V scratch: exact 144B fp16 row images ----
__device__ __align__(16) char g_ksh[NB * 128 * STR];
__device__ __align__(16) char g_vsh[NB * 128 * STR];

__device__ __forceinline__ uint32_t smem_u32(const void* p) {
    uint32_t a;
    asm("{ .reg .u64 t; cvta.to.shared.u64 t, %1; cvt.u32.u64 %0, t; }" : "=r"(a) : "l"(p));
    return a;
}
__device__ __forceinline__ uint32_t pk2h(float a, float b) {
    __half2 t = __floats2half2_rn(a, b);
    return *(uint32_t*)&t;
}
__device__ __forceinline__ float2 unpk2h(uint32_t u) {
    __half2 t = *(__half2*)&u;
    return __half22float2(t);
}
__device__ __forceinline__ float ex2a(float x) {
    float r; asm("ex2.approx.f32 %0, %1;" : "=f"(r) : "f"(x)); return r;
}
#define CP16(dst, src)                                                       \
    asm volatile("cp.async.cg.shared.global [%0], [%1], 16;"                 \
                 :: "r"(dst), "l"(src) : "memory")

#define MMAF16(d0,d1,d2,d3,a0,a1,a2,a3,b0,b1)                                \
    asm volatile("mma.sync.aligned.m16n8k16.row.col.f32.f16.f16.f32 "        \
                 "{%0,%1,%2,%3}, {%4,%5,%6,%7}, {%8,%9}, {%0,%1,%2,%3};"     \
                 : "+f"(d0), "+f"(d1), "+f"(d2), "+f"(d3)                    \
                 : "r"(a0), "r"(a1), "r"(a2), "r"(a3), "r"(b0), "r"(b1))

#define LDSM4(r0,r1,r2,r3,addr)                                              \
    asm volatile("ldmatrix.sync.aligned.m8n8.x4.shared.b16 {%0,%1,%2,%3}, [%4];" \
                 : "=r"(r0), "=r"(r1), "=r"(r2), "=r"(r3) : "r"(addr))

#define LDSM4T(r0,r1,r2,r3,addr)                                             \
    asm volatile("ldmatrix.sync.aligned.m8n8.x4.trans.shared.b16 {%0,%1,%2,%3}, [%4];" \
                 : "=r"(r0), "=r"(r1), "=r"(r2), "=r"(r3) : "r"(addr))

// ---------------- pre-pass: convert gathered K/V to fp16 row images ----------------
__global__ __launch_bounds__(256)
void cba_prep(const float* __restrict__ Kg, const float* __restrict__ Vg)
{
    const int u = (int)blockIdx.x * 256 + (int)threadIdx.x;   // NB*128*16 units
    const int b = u >> 11;
    const int rem = u & 2047;
    const int j = rem >> 4;
    const int e4 = (rem & 15) << 2;
    const size_t goff = ((size_t)(b * NT + 64 * j + 63)) * NE + e4;
    const size_t soff = (size_t)(b * 128 + j) * STR + e4 * 2;

    const float4 k4 = *(const float4*)(Kg + goff);
    *(uint2*)(g_ksh + soff) = make_uint2(pk2h(k4.x, k4.y), pk2h(k4.z, k4.w));
    const float4 v4 = *(const float4*)(Vg + goff);
    *(uint2*)(g_vsh + soff) = make_uint2(pk2h(v4.x, v4.y), pk2h(v4.z, v4.w));
}

// ---------------- consumer: one warp, 16 rows, Np = 16G columns ----------------
template<int G>
__device__ __forceinline__ void warp_work(uint32_t smb, int R, int lane, int i0,
                                          const uint32_t qh[4][4],
                                          float* __restrict__ OutB, float* __restrict__ AB)
{
    const int g  = lane >> 2;
    const int tg = lane & 3;
    const int nv_lo = (i0 + R + g + 1) >> 6;
    const int nv_hi = (i0 + R + g + 8 + 1) >> 6;

    const uint32_t ka = smb + KOFF + (uint32_t)((lane & 7) * STR + (lane >> 3) * 16);
    const uint32_t va = smb + VOFF +
        (uint32_t)(((lane & 7) + ((lane >> 3) & 1) * 8) * STR + (lane >> 4) * 16);

    uint32_t p01[2 * G], p23[2 * G];
    float sum_lo = 0.0f, sum_hi = 0.0f;

    // ---- MMA1: n-tile pairs, 2 independent 4-chains; S in log2 domain ----
#pragma unroll
    for (int np = 0; np < G; ++np) {
        const int n0 = 2 * np;
        const uint32_t kan0 = ka + (uint32_t)(n0 * 8 * STR);
        const uint32_t kan1 = kan0 + 8 * STR;
        uint32_t k0[8], k1[8];
        LDSM4(k0[0], k0[1], k0[2], k0[3], kan0);
        LDSM4(k0[4], k0[5], k0[6], k0[7], kan0 + 64);
        LDSM4(k1[0], k1[1], k1[2], k1[3], kan1);
        LDSM4(k1[4], k1[5], k1[6], k1[7], kan1 + 64);

        float d0[4] = {0.f, 0.f, 0.f, 0.f};
        float d1[4] = {0.f, 0.f, 0.f, 0.f};
#pragma unroll
        for (int k = 0; k < 4; ++k) {
            MMAF16(d0[0], d0[1], d0[2], d0[3],
                   qh[k][0], qh[k][1], qh[k][2], qh[k][3], k0[2 * k], k0[2 * k + 1]);
            MMAF16(d1[0], d1[1], d1[2], d1[3],
                   qh[k][0], qh[k][1], qh[k][2], qh[k][3], k1[2 * k], k1[2 * k + 1]);
        }

#pragma unroll
        for (int h = 0; h < 2; ++h) {
            const float* d = h ? d1 : d0;
            const int n = n0 + h;
            const int j0 = 8 * n + 2 * tg;
            const float e0 = (j0     < nv_lo) ? ex2a(d[0]) : 0.0f;
            const float e1 = (j0 + 1 < nv_lo) ? ex2a(d[1]) : 0.0f;
            const float e2 = (j0     < nv_hi) ? ex2a(d[2]) : 0.0f;
            const float e3 = (j0 + 1 < nv_hi) ? ex2a(d[3]) : 0.0f;
            sum_lo += e0 + e1;
            sum_hi += e2 + e3;
            p01[n] = pk2h(e0, e1);
            p23[n] = pk2h(e2, e3);
        }
    }

    sum_lo += __shfl_xor_sync(0xffffffffu, sum_lo, 1);
    sum_lo += __shfl_xor_sync(0xffffffffu, sum_lo, 2);
    sum_hi += __shfl_xor_sync(0xffffffffu, sum_hi, 1);
    sum_hi += __shfl_xor_sync(0xffffffffu, sum_hi, 2);
    const float inv_lo = (nv_lo > 0) ? 1.0f / sum_lo : 0.0f;
    const float inv_hi = (nv_hi > 0) ? 1.0f / sum_hi : 0.0f;

    // ---- MMA2: Out = Ehat * V (A frags straight from exp regs) ----
    float o[8][4];
#pragma unroll
    for (int nt = 0; nt < 8; ++nt)
#pragma unroll
        for (int t = 0; t < 4; ++t) o[nt][t] = 0.0f;

#pragma unroll
    for (int kk = 0; kk < G; ++kk) {
        const uint32_t a0 = p01[2 * kk], a1 = p23[2 * kk];
        const uint32_t a2 = p01[2 * kk + 1], a3 = p23[2 * kk + 1];
        const uint32_t vak = va + (uint32_t)(kk * 16 * STR);

        uint32_t vh[16];
        LDSM4T(vh[0],  vh[1],  vh[2],  vh[3],  vak);
        LDSM4T(vh[4],  vh[5],  vh[6],  vh[7],  vak + 32);
        LDSM4T(vh[8],  vh[9],  vh[10], vh[11], vak + 64);
        LDSM4T(vh[12], vh[13], vh[14], vh[15], vak + 96);
#pragma unroll
        for (int nt = 0; nt < 8; ++nt) {
            const uint32_t b0 = vh[(nt >> 1) * 4 + (nt & 1) * 2];
            const uint32_t b1 = vh[(nt >> 1) * 4 + (nt & 1) * 2 + 1];
            MMAF16(o[nt][0], o[nt][1], o[nt][2], o[nt][3], a0, a1, a2, a3, b0, b1);
        }
    }

    // ---- write Out (normalized) ----
#pragma unroll
    for (int nt = 0; nt < 8; ++nt) {
        const int e = 8 * nt + 2 * tg;
        *(float2*)(OutB + (size_t)(R + g) * NE + e)     = make_float2(o[nt][0] * inv_lo, o[nt][1] * inv_lo);
        *(float2*)(OutB + (size_t)(R + g + 8) * NE + e) = make_float2(o[nt][2] * inv_hi, o[nt][3] * inv_hi);
    }
    // ---- write A (normalized) ----
#pragma unroll
    for (int n = 0; n < 2 * G; ++n) {
        const int j = 8 * n + 2 * tg;
        float2 v = unpk2h(p01[n]);
        *(float2*)(AB + (size_t)(R + g) * NC + j) = make_float2(v.x * inv_lo, v.y * inv_lo);
        v = unpk2h(p23[n]);
        *(float2*)(AB + (size_t)(R + g + 8) * NC + j) = make_float2(v.x * inv_hi, v.y * inv_hi);
    }
    // ---- zero tail columns [16G, 128) of A ----
    if (G < 8) {
        const int Np = 16 * G;
        const int t4 = (NC - Np) >> 2;
        for (int t = lane; t < 16 * t4; t += 32) {
            const int row = t / t4, cq = t - row * t4;
            *(float4*)(AB + (size_t)(R + row) * NC + Np + 4 * cq) =
                make_float4(0.f, 0.f, 0.f, 0.f);
        }
    }
}

// ---------------- main kernel ----------------
__global__ __launch_bounds__(256, 2)
void cba_mma(const float* __restrict__ Qg, float* __restrict__ Outg,
             float* __restrict__ Ag)
{
    extern __shared__ char sm[];
    const int tid  = (int)threadIdx.x;
    const int lane = tid & 31;
    const int w    = tid >> 5;
    const int p    = 63 - (int)blockIdx.x;
    const int b    = (int)blockIdx.y;
    const int c    = 2 * p + 2;
    const int G    = (c + 15) >> 4;
    const int Np   = G << 4;
    const int i0   = p << 7;
    const int g    = lane >> 2;
    const int tg   = lane & 3;
    const int R    = w << 4;
    const uint32_t smb = smem_u32(sm);

    // ---- stage K/V via cp.async from pre-converted scratch (first: deepest latency) ----
    {
        const size_t boff = (size_t)b * 128 * STR;
        const char* kh = g_ksh + boff;
        const char* vh = g_vsh + boff;
        const int nchunk = c * 9;               // 16B chunks per region
        for (int idx = tid; idx < nchunk; idx += 256) {
            const uint32_t off = (uint32_t)idx * 16;
            CP16(smb + KOFF + off, kh + off);
            CP16(smb + VOFF + off, vh + off);
        }
        asm volatile("cp.async.commit_group;" ::: "memory");
        // zero pad rows [c, Np) (V pads are load-bearing for MMA2)
        const int padchunk = (Np - c) * 9;
        for (int idx = tid; idx < padchunk; idx += 256) {
            const uint32_t off = (uint32_t)(c * 9 + idx) * 16;
            *(uint4*)(sm + KOFF + off) = make_uint4(0u, 0u, 0u, 0u);
            *(uint4*)(sm + VOFF + off) = make_uint4(0u, 0u, 0u, 0u);
        }
    }

    // ---- Q fragments from gmem, converted to fp16 (log2-domain prescale) ----
    uint32_t qh[4][4];
    {
        const float* Qb = Qg + (size_t)(b * NT + i0) * NE;
        float2 qf[4][4];
#pragma unroll
        for (int k = 0; k < 4; ++k) {
            const float* q0 = Qb + (size_t)(R + g) * NE + 16 * k + 2 * tg;
            const float* q8 = q0 + 8 * NE;
            qf[k][0] = *(const float2*)q0;
            qf[k][1] = *(const float2*)q8;
            qf[k][2] = *(const float2*)(q0 + 8);
            qf[k][3] = *(const float2*)(q8 + 8);
        }
#pragma unroll
        for (int k = 0; k < 4; ++k)
#pragma unroll
            for (int t = 0; t < 4; ++t)
                qh[k][t] = pk2h(qf[k][t].x * QSCALE, qf[k][t].y * QSCALE);
    }

    asm volatile("cp.async.wait_group 0;" ::: "memory");
    __syncthreads();

    float* OutB = Outg + (size_t)(b * NT + i0) * NE;
    float* AB   = Ag   + (size_t)(b * NT + i0) * NC;

    switch (G) {
    case 1: warp_work<1>(smb, R, lane, i0, qh, OutB, AB); break;
    case 2: warp_work<2>(smb, R, lane, i0, qh, OutB, AB); break;
    case 3: warp_work<3>(smb, R, lane, i0, qh, OutB, AB); break;
    case 4: warp_work<4>(smb, R, lane, i0, qh, OutB, AB); break;
    case 5: warp_work<5>(smb, R, lane, i0, qh, OutB, AB); break;
    case 6: warp_work<6>(smb, R, lane, i0, qh, OutB, AB); break;
    case 7: warp_work<7>(smb, R, lane, i0, qh, OutB, AB); break;
    default: warp_work<8>(smb, R, lane, i0, qh, OutB, AB); break;
    }
}

extern "C" void kernel_launch(void* const* d_in, const int* in_sizes, int n_in,
                              void* d_out, int out_size)
{
    const float* Q = (const float*)d_in[0];
    const float* K = (const float*)d_in[1];
    const float* V = (const float*)d_in[2];
    float* Out = (float*)d_out;
    float* A   = Out + (size_t)NB * NT * NE;

    cba_prep<<<128, 256>>>(K, V);

    cudaFuncSetAttribute(cba_mma, cudaFuncAttributeMaxDynamicSharedMemorySize, SMEM_TOTAL);
    dim3 grid(64, NB);
    cba_mma<<<grid, 256, SMEM_TOTAL>>>(Q, Out, A);
}